// round 16
// baseline (speedup 1.0000x reference)
#include <cuda_runtime.h>
#include <cuda_bf16.h>
#include <cstdint>

// Problem constants (fixed shapes)
#define BB     16
#define TT     512
#define EE     768
#define TWO_E  1536
#define NENT   512
#define PTOT   15872
#define HH     512
#define OUTD   512      // 2*ENTITY_DIM

// Scratch: Arel, Brel, Asc, Bsc  each [512][512] f32  (4 MB total)
__device__ float g_scratch[4 * 512 * 512];
// Packed W2^T bf16 hi/lo, layout [n][k]  (n rows of 512 k)
__device__ __nv_bfloat16 g_w2hi[512 * 512];
__device__ __nv_bfloat16 g_w2lo[512 * 512];
// Packed first-layer weights, transposed: [mat*512 + n][k], k = 0..1535
// mat 0: W1 top, 1: W1 bottom, 2: Ws1 top, 3: Ws1 bottom
__device__ __nv_bfloat16 g_prehi[4 * 512 * 1536];
__device__ __nv_bfloat16 g_prelo[4 * 512 * 1536];
// Packed entity matrix [m][k] bf16 hi/lo (m=512, k=1536)
__device__ __nv_bfloat16 g_enthi[512 * 1536];
__device__ __nv_bfloat16 g_entlo[512 * 1536];

// ---------------------------------------------------------------------------
// helpers
// ---------------------------------------------------------------------------
__device__ __forceinline__ void split4(float4 v, uint2& h, uint2& l) {
    __nv_bfloat16 hx = __float2bfloat16(v.x), hy = __float2bfloat16(v.y);
    __nv_bfloat16 hz = __float2bfloat16(v.z), hw = __float2bfloat16(v.w);
    __nv_bfloat16 lx = __float2bfloat16(v.x - __bfloat162float(hx));
    __nv_bfloat16 ly = __float2bfloat16(v.y - __bfloat162float(hy));
    __nv_bfloat16 lz = __float2bfloat16(v.z - __bfloat162float(hz));
    __nv_bfloat16 lw = __float2bfloat16(v.w - __bfloat162float(hw));
    __nv_bfloat162 h01; h01.x = hx; h01.y = hy;
    __nv_bfloat162 h23; h23.x = hz; h23.y = hw;
    __nv_bfloat162 l01; l01.x = lx; l01.y = ly;
    __nv_bfloat162 l23; l23.x = lz; l23.y = lw;
    h = make_uint2(*(uint32_t*)&h01, *(uint32_t*)&h23);
    l = make_uint2(*(uint32_t*)&l01, *(uint32_t*)&l23);
}

__device__ __forceinline__ void mma16816(float& c0, float& c1, float& c2, float& c3,
                                         uint32_t a0, uint32_t a1, uint32_t a2, uint32_t a3,
                                         uint32_t b0, uint32_t b1) {
    asm volatile(
        "mma.sync.aligned.m16n8k16.row.col.f32.bf16.bf16.f32 "
        "{%0,%1,%2,%3}, {%4,%5,%6,%7}, {%8,%9}, {%0,%1,%2,%3};"
        : "+f"(c0), "+f"(c1), "+f"(c2), "+f"(c3)
        : "r"(a0), "r"(a1), "r"(a2), "r"(a3), "r"(b0), "r"(b1));
}

// ---------------------------------------------------------------------------
// Kernel A: gather entity representations  ent[i] = [x[b,t0], x[b,t1]]
// and emit bf16 hi/lo packed copy for the precompute GEMM.
// ---------------------------------------------------------------------------
__global__ void k_gather(const float* __restrict__ x, const int* __restrict__ ann,
                         float* __restrict__ ent) {
    int i = blockIdx.x;
    int b = i >> 5, a = i & 31;
    int t0 = ann[b * 64 + 2 * a];
    int t1 = ann[b * 64 + 2 * a + 1];
    const float4* r0 = reinterpret_cast<const float4*>(x + ((long)b * TT + t0) * EE);
    const float4* r1 = reinterpret_cast<const float4*>(x + ((long)b * TT + t1) * EE);
    float4* o = reinterpret_cast<float4*>(ent + (long)i * TWO_E);
    __nv_bfloat16* eh = g_enthi + (long)i * TWO_E;
    __nv_bfloat16* el = g_entlo + (long)i * TWO_E;
    for (int j = threadIdx.x; j < 192; j += blockDim.x) {
        float4 v0 = r0[j];
        float4 v1 = r1[j];
        o[j] = v0;
        o[192 + j] = v1;
        uint2 h, l;
        split4(v0, h, l);
        *(uint2*)(eh + j * 4) = h;
        *(uint2*)(el + j * 4) = l;
        split4(v1, h, l);
        *(uint2*)(eh + 768 + j * 4) = h;
        *(uint2*)(el + 768 + j * 4) = l;
    }
}

// ---------------------------------------------------------------------------
// Pack W1/Ws1 into [mat*512+n][k] bf16 hi/lo (transposed).
// j -> n fastest (coalesced reads). 393216 jobs.
// ---------------------------------------------------------------------------
__global__ void k_packw1(const float* __restrict__ W1, const float* __restrict__ Ws1) {
    int j = blockIdx.x * 256 + threadIdx.x;
    int n = j & 511;
    int rest = j >> 9;
    int kg = rest % 192;
    int mat = rest / 192;
    const float* W = ((mat < 2) ? W1 : Ws1) + (long)(mat & 1) * (1536 * 512);
    int k0 = kg * 8;
    __nv_bfloat16 hi[8], lo[8];
#pragma unroll
    for (int q = 0; q < 8; q++) {
        float v = W[(long)(k0 + q) * 512 + n];
        hi[q] = __float2bfloat16(v);
        lo[q] = __float2bfloat16(v - __bfloat162float(hi[q]));
    }
    long off = (long)(mat * 512 + n) * 1536 + k0;
    *(uint4*)&g_prehi[off] = *(uint4*)hi;
    *(uint4*)&g_prelo[off] = *(uint4*)lo;
}

// ---------------------------------------------------------------------------
// Pack W2 (k-major [k][n]) into bf16 hi/lo [n][k].
// ---------------------------------------------------------------------------
__global__ void k_packw2(const float* __restrict__ W2) {
    int t = blockIdx.x * 256 + threadIdx.x;   // 0..131071
    int n = t >> 8;
    int k = (t & 255) * 2;
    float v0 = W2[(long)k * 512 + n];
    float v1 = W2[(long)(k + 1) * 512 + n];
    __nv_bfloat16 h0 = __float2bfloat16(v0), h1 = __float2bfloat16(v1);
    float r0 = v0 - __bfloat162float(h0);
    float r1 = v1 - __bfloat162float(h1);
    __nv_bfloat16 l0 = __float2bfloat16(r0), l1 = __float2bfloat16(r1);
    __nv_bfloat162 ph; ph.x = h0; ph.y = h1;
    __nv_bfloat162 pl; pl.x = l0; pl.y = l1;
    *(uint32_t*)&g_w2hi[(long)n * 512 + k] = *(uint32_t*)&ph;
    *(uint32_t*)&g_w2lo[(long)n * 512 + k] = *(uint32_t*)&pl;
}

#define PADK 40   // row stride in bf16 elements (80 bytes) -> conflict-free frags

// ---------------------------------------------------------------------------
// Kernel B (HMMA): precompute  g_scratch[mat] = ent @ W_block  (3xBF16)
// grid (32, 4): x = 64-col block over 2048 total cols, y = 128-row block
// block 256 (8 warps: 4 m x 2 n), warp tile 32m x 32n, K=1536 chunks of 32
// ---------------------------------------------------------------------------
__global__ void __launch_bounds__(256, 1) k_pre_hmma() {
    __shared__ __nv_bfloat16 sAh[128][PADK];
    __shared__ __nv_bfloat16 sAl[128][PADK];
    __shared__ __nv_bfloat16 sBh[64][PADK];
    __shared__ __nv_bfloat16 sBl[64][PADK];

    int tid = threadIdx.x;
    int wid = tid >> 5, lane = tid & 31;
    int g = lane >> 2, tq = lane & 3;
    int bm = blockIdx.y * 128;
    int nb = blockIdx.x;
    int wm = (wid & 3) * 32;
    int wn = (wid >> 2) * 32;

    // A load assignment: row m, 16-k half
    int m = tid >> 1;
    int kh = (tid & 1) * 16;
    const __nv_bfloat16* gAh = g_enthi + (long)(bm + m) * 1536 + kh;
    const __nv_bfloat16* gAl = g_entlo + (long)(bm + m) * 1536 + kh;
    // B load assignment: row br (of 64), 8-k quarter
    int br = tid >> 2;
    int koff = (tid & 3) * 8;
    int ng = nb * 64 + br;   // global col 0..2047 == packed row index
    const __nv_bfloat16* gBh = g_prehi + (long)ng * 1536 + koff;
    const __nv_bfloat16* gBl = g_prelo + (long)ng * 1536 + koff;

    float acc[2][4][4];
#pragma unroll
    for (int mt = 0; mt < 2; mt++)
#pragma unroll
        for (int nt = 0; nt < 4; nt++)
#pragma unroll
            for (int q = 0; q < 4; q++) acc[mt][nt][q] = 0.f;

    for (int kc = 0; kc < 1536; kc += 32) {
        uint4 ah0 = *(const uint4*)(gAh + kc);
        uint4 ah1 = *(const uint4*)(gAh + kc + 8);
        uint4 al0 = *(const uint4*)(gAl + kc);
        uint4 al1 = *(const uint4*)(gAl + kc + 8);
        uint4 bh = *(const uint4*)(gBh + kc);
        uint4 bl = *(const uint4*)(gBl + kc);

        __syncthreads();
        *(uint4*)&sAh[m][kh]     = ah0;
        *(uint4*)&sAh[m][kh + 8] = ah1;
        *(uint4*)&sAl[m][kh]     = al0;
        *(uint4*)&sAl[m][kh + 8] = al1;
        *(uint4*)&sBh[br][koff] = bh;
        *(uint4*)&sBl[br][koff] = bl;
        __syncthreads();

#pragma unroll
        for (int ks = 0; ks < 32; ks += 16) {
            uint32_t ah[2][4], al[2][4];
#pragma unroll
            for (int mt = 0; mt < 2; mt++) {
                int r0 = wm + mt * 16 + g;
                ah[mt][0] = *(uint32_t*)&sAh[r0][ks + 2 * tq];
                ah[mt][1] = *(uint32_t*)&sAh[r0 + 8][ks + 2 * tq];
                ah[mt][2] = *(uint32_t*)&sAh[r0][ks + 2 * tq + 8];
                ah[mt][3] = *(uint32_t*)&sAh[r0 + 8][ks + 2 * tq + 8];
                al[mt][0] = *(uint32_t*)&sAl[r0][ks + 2 * tq];
                al[mt][1] = *(uint32_t*)&sAl[r0 + 8][ks + 2 * tq];
                al[mt][2] = *(uint32_t*)&sAl[r0][ks + 2 * tq + 8];
                al[mt][3] = *(uint32_t*)&sAl[r0 + 8][ks + 2 * tq + 8];
            }
#pragma unroll
            for (int nt = 0; nt < 4; nt++) {
                int nr = wn + nt * 8 + g;
                uint32_t bh0 = *(uint32_t*)&sBh[nr][ks + 2 * tq];
                uint32_t bh1 = *(uint32_t*)&sBh[nr][ks + 2 * tq + 8];
                uint32_t bl0 = *(uint32_t*)&sBl[nr][ks + 2 * tq];
                uint32_t bl1 = *(uint32_t*)&sBl[nr][ks + 2 * tq + 8];
#pragma unroll
                for (int mt = 0; mt < 2; mt++) {
                    float* c = acc[mt][nt];
                    mma16816(c[0], c[1], c[2], c[3],
                             ah[mt][0], ah[mt][1], ah[mt][2], ah[mt][3], bh0, bh1);
                    mma16816(c[0], c[1], c[2], c[3],
                             ah[mt][0], ah[mt][1], ah[mt][2], ah[mt][3], bl0, bl1);
                    mma16816(c[0], c[1], c[2], c[3],
                             al[mt][0], al[mt][1], al[mt][2], al[mt][3], bh0, bh1);
                }
            }
        }
    }

    // store to g_scratch: col -> (mat = col>>9, cim = col&511)
#pragma unroll
    for (int nt = 0; nt < 4; nt++) {
        int col = nb * 64 + wn + nt * 8 + 2 * tq;
        long base = (long)(col >> 9) * 262144 + (col & 511);
#pragma unroll
        for (int mt = 0; mt < 2; mt++) {
            int row = bm + wm + mt * 16 + g;
            float* c = acc[mt][nt];
            *(float2*)&g_scratch[base + (long)row * 512] = make_float2(c[0], c[1]);
            *(float2*)&g_scratch[base + (long)(row + 8) * 512] = make_float2(c[2], c[3]);
        }
    }
}

// ---------------------------------------------------------------------------
// Kernel C (HMMA): relation_representation
//   CTA tile: M=128 pairs x N=128 cols, K=512 in chunks of 32.
//   H chunk = relu(A[l]+B[r]+b1) built SIMT, split bf16 hi/lo in SMEM.
//   3xBF16: acc += Ah*Bh + Ah*Bl + Al*Bh  (fp32 accum in registers).
// grid (4, 124), block 256 (8 warps: 4 m-warps x 2 n-warps)
// ---------------------------------------------------------------------------
__global__ void __launch_bounds__(256, 1) k_pairs_hmma(
    const int* __restrict__ left, const int* __restrict__ right,
    const float* __restrict__ b1, const float* __restrict__ b2,
    float* __restrict__ out_rel)
{
    __shared__ __nv_bfloat16 sAh[128][PADK];
    __shared__ __nv_bfloat16 sAl[128][PADK];
    __shared__ __nv_bfloat16 sBh[128][PADK];
    __shared__ __nv_bfloat16 sBl[128][PADK];
    __shared__ float b1s[512];

    int tid = threadIdx.x;
    int wid = tid >> 5, lane = tid & 31;
    int g = lane >> 2, tq = lane & 3;
    int bp = blockIdx.y * 128;
    int nb = blockIdx.x;           // n block (128 cols)
    int wm = (wid & 3) * 32;       // warp m offset
    int wn = (wid >> 2) * 64;      // warp n offset

    // H-build assignment
    int m = tid >> 1;
    int kh = (tid & 1) * 16;
    int lm = left[bp + m];
    int rm = right[bp + m];
    const float* Ar = g_scratch + (long)lm * 512;
    const float* Br = g_scratch + 262144 + (long)rm * 512;

    // B-tile load assignment: row r, half (tid&1)
    int br = tid >> 1;
    int bh_off = (tid & 1) * 16;
    const __nv_bfloat16* gBh = g_w2hi + (long)(nb * 128 + br) * 512 + bh_off;
    const __nv_bfloat16* gBl = g_w2lo + (long)(nb * 128 + br) * 512 + bh_off;

    if (tid < 128) ((float4*)b1s)[tid] = ((const float4*)b1)[tid];
    __syncthreads();   // b1s visible to ALL warps before first H-build (race fix)

    float acc[2][8][4];
#pragma unroll
    for (int mt = 0; mt < 2; mt++)
#pragma unroll
        for (int nt = 0; nt < 8; nt++)
#pragma unroll
            for (int q = 0; q < 4; q++) acc[mt][nt][q] = 0.f;

    for (int kc = 0; kc < 512; kc += 32) {
        // ---- stage B chunk through registers (overlap with H build) ----
        uint4 wbh0 = *(const uint4*)(gBh + kc);
        uint4 wbh1 = *(const uint4*)(gBh + kc + 8);
        uint4 wbl0 = *(const uint4*)(gBl + kc);
        uint4 wbl1 = *(const uint4*)(gBl + kc + 8);

        // ---- build H (relu(A[l]+B[r]+b1)), split hi/lo ----
        int kg = kc + kh;
        float4 x0 = *(const float4*)(Ar + kg);
        float4 x1 = *(const float4*)(Ar + kg + 4);
        float4 x2 = *(const float4*)(Ar + kg + 8);
        float4 x3 = *(const float4*)(Ar + kg + 12);
        float4 y0 = *(const float4*)(Br + kg);
        float4 y1 = *(const float4*)(Br + kg + 4);
        float4 y2 = *(const float4*)(Br + kg + 8);
        float4 y3 = *(const float4*)(Br + kg + 12);
        float h[16];
        h[0]  = x0.x + y0.x; h[1]  = x0.y + y0.y; h[2]  = x0.z + y0.z; h[3]  = x0.w + y0.w;
        h[4]  = x1.x + y1.x; h[5]  = x1.y + y1.y; h[6]  = x1.z + y1.z; h[7]  = x1.w + y1.w;
        h[8]  = x2.x + y2.x; h[9]  = x2.y + y2.y; h[10] = x2.z + y2.z; h[11] = x2.w + y2.w;
        h[12] = x3.x + y3.x; h[13] = x3.y + y3.y; h[14] = x3.z + y3.z; h[15] = x3.w + y3.w;
        uint32_t hiw[8], low[8];
#pragma unroll
        for (int q = 0; q < 8; q++) {
            float v0 = fmaxf(h[2 * q]     + b1s[kg + 2 * q],     0.f);
            float v1 = fmaxf(h[2 * q + 1] + b1s[kg + 2 * q + 1], 0.f);
            __nv_bfloat16 e0 = __float2bfloat16(v0);
            __nv_bfloat16 e1 = __float2bfloat16(v1);
            __nv_bfloat16 f0 = __float2bfloat16(v0 - __bfloat162float(e0));
            __nv_bfloat16 f1 = __float2bfloat16(v1 - __bfloat162float(e1));
            __nv_bfloat162 ph; ph.x = e0; ph.y = e1;
            __nv_bfloat162 pl; pl.x = f0; pl.y = f1;
            hiw[q] = *(uint32_t*)&ph;
            low[q] = *(uint32_t*)&pl;
        }

        __syncthreads();   // previous chunk's MMAs done reading SMEM

        *(uint4*)&sAh[m][kh]     = make_uint4(hiw[0], hiw[1], hiw[2], hiw[3]);
        *(uint4*)&sAh[m][kh + 8] = make_uint4(hiw[4], hiw[5], hiw[6], hiw[7]);
        *(uint4*)&sAl[m][kh]     = make_uint4(low[0], low[1], low[2], low[3]);
        *(uint4*)&sAl[m][kh + 8] = make_uint4(low[4], low[5], low[6], low[7]);
        *(uint4*)&sBh[br][bh_off]     = wbh0;
        *(uint4*)&sBh[br][bh_off + 8] = wbh1;
        *(uint4*)&sBl[br][bh_off]     = wbl0;
        *(uint4*)&sBl[br][bh_off + 8] = wbl1;

        __syncthreads();

        // ---- MMA over the 32-wide chunk (two k16 steps) ----
#pragma unroll
        for (int ks = 0; ks < 32; ks += 16) {
            uint32_t ah[2][4], al[2][4];
#pragma unroll
            for (int mt = 0; mt < 2; mt++) {
                int r0 = wm + mt * 16 + g;
                ah[mt][0] = *(uint32_t*)&sAh[r0][ks + 2 * tq];
                ah[mt][1] = *(uint32_t*)&sAh[r0 + 8][ks + 2 * tq];
                ah[mt][2] = *(uint32_t*)&sAh[r0][ks + 2 * tq + 8];
                ah[mt][3] = *(uint32_t*)&sAh[r0 + 8][ks + 2 * tq + 8];
                al[mt][0] = *(uint32_t*)&sAl[r0][ks + 2 * tq];
                al[mt][1] = *(uint32_t*)&sAl[r0 + 8][ks + 2 * tq];
                al[mt][2] = *(uint32_t*)&sAl[r0][ks + 2 * tq + 8];
                al[mt][3] = *(uint32_t*)&sAl[r0 + 8][ks + 2 * tq + 8];
            }
#pragma unroll
            for (int nt = 0; nt < 8; nt++) {
                int nr = wn + nt * 8 + g;
                uint32_t bh0 = *(uint32_t*)&sBh[nr][ks + 2 * tq];
                uint32_t bh1 = *(uint32_t*)&sBh[nr][ks + 2 * tq + 8];
                uint32_t bl0 = *(uint32_t*)&sBl[nr][ks + 2 * tq];
                uint32_t bl1 = *(uint32_t*)&sBl[nr][ks + 2 * tq + 8];
#pragma unroll
                for (int mt = 0; mt < 2; mt++) {
                    float* c = acc[mt][nt];
                    mma16816(c[0], c[1], c[2], c[3],
                             ah[mt][0], ah[mt][1], ah[mt][2], ah[mt][3], bh0, bh1);
                    mma16816(c[0], c[1], c[2], c[3],
                             ah[mt][0], ah[mt][1], ah[mt][2], ah[mt][3], bl0, bl1);
                    mma16816(c[0], c[1], c[2], c[3],
                             al[mt][0], al[mt][1], al[mt][2], al[mt][3], bh0, bh1);
                }
            }
        }
    }

    // ---- epilogue: add b2, store ----
#pragma unroll
    for (int nt = 0; nt < 8; nt++) {
        int col = nb * 128 + wn + nt * 8 + 2 * tq;
        float bb0 = __ldg(&b2[col]);
        float bb1 = __ldg(&b2[col + 1]);
#pragma unroll
        for (int mt = 0; mt < 2; mt++) {
            int row = bp + wm + mt * 16 + g;
            float* c = acc[mt][nt];
            float2 v0 = make_float2(c[0] + bb0, c[1] + bb1);
            float2 v1 = make_float2(c[2] + bb0, c[3] + bb1);
            *(float2*)(out_rel + (long)row * 512 + col) = v0;
            *(float2*)(out_rel + (long)(row + 8) * 512 + col) = v1;
        }
    }
}

// ---------------------------------------------------------------------------
// Kernel D: relation_score.  One warp per pair.
// ---------------------------------------------------------------------------
__global__ void k_score(const int* __restrict__ left, const int* __restrict__ right,
                        const float* __restrict__ bs1, const float* __restrict__ Ws2,
                        const float* __restrict__ bs2, float* __restrict__ score) {
    const float* Asc = g_scratch + 2 * 512 * 512;
    const float* Bsc = g_scratch + 3 * 512 * 512;
    int warp = threadIdx.x >> 5, lane = threadIdx.x & 31;
    int p = blockIdx.x * 8 + warp;
    if (p >= PTOT) return;
    long l = left[p], r = right[p];
    float s = 0.f;
#pragma unroll
    for (int k = lane * 4; k < 512; k += 128) {
        float4 a = *reinterpret_cast<const float4*>(Asc + l * 512 + k);
        float4 b = *reinterpret_cast<const float4*>(Bsc + r * 512 + k);
        float4 bb = *reinterpret_cast<const float4*>(bs1 + k);
        float4 w = *reinterpret_cast<const float4*>(Ws2 + k);
        s = fmaf(fmaxf(a.x + b.x + bb.x, 0.f), w.x, s);
        s = fmaf(fmaxf(a.y + b.y + bb.y, 0.f), w.y, s);
        s = fmaf(fmaxf(a.z + b.z + bb.z, 0.f), w.z, s);
        s = fmaf(fmaxf(a.w + b.w + bb.w, 0.f), w.w, s);
    }
#pragma unroll
    for (int o = 16; o > 0; o >>= 1) s += __shfl_down_sync(0xffffffffu, s, o);
    if (lane == 0) score[p] = fabsf(s + bs2[0]);
}

// ---------------------------------------------------------------------------
extern "C" void kernel_launch(void* const* d_in, const int* in_sizes, int n_in,
                              void* d_out, int out_size) {
    const float* x   = (const float*)d_in[0];
    const int*   ann = (const int*)d_in[3];
    int p = (in_sizes[4] == 1) ? 5 : 4;
    const int*   left  = (const int*)d_in[p + 0];
    const int*   right = (const int*)d_in[p + 1];
    const float* W1  = (const float*)d_in[p + 2];
    const float* b1  = (const float*)d_in[p + 3];
    const float* W2  = (const float*)d_in[p + 4];
    const float* b2  = (const float*)d_in[p + 5];
    const float* Ws1 = (const float*)d_in[p + 6];
    const float* bs1 = (const float*)d_in[p + 7];
    const float* Ws2 = (const float*)d_in[p + 8];
    const float* bs2 = (const float*)d_in[p + 9];

    float* out   = (float*)d_out;
    float* ent   = out;                                  // [512, 1536]
    float* rel   = out + (long)NENT * TWO_E;             // [15872, 512]
    float* score = rel + (long)PTOT * OUTD;              // [15872]

    k_packw1<<<1536, 256>>>(W1, Ws1);
    k_packw2<<<512, 256>>>(W2);
    k_gather<<<NENT, 192>>>(x, ann, ent);
    k_pre_hmma<<<dim3(32, 4), 256>>>();
    k_pairs_hmma<<<dim3(4, 124), 256>>>(left, right, b1, b2, rel);
    k_score<<<PTOT / 8, 256>>>(left, right, bs1, Ws2, bs2, score);
}

// round 17
// speedup vs baseline: 1.0028x; 1.0028x over previous
#include <cuda_runtime.h>
#include <cuda_bf16.h>
#include <cstdint>

// Problem constants (fixed shapes)
#define BB     16
#define TT     512
#define EE     768
#define TWO_E  1536
#define NENT   512
#define PTOT   15872
#define HH     512
#define OUTD   512      // 2*ENTITY_DIM

// Scratch: Arel, Brel, Asc, Bsc  each [512][512] f32  (4 MB total)
__device__ float g_scratch[4 * 512 * 512];
// Packed W2^T bf16 hi/lo, layout [n][k]  (n rows of 512 k)
__device__ __nv_bfloat16 g_w2hi[512 * 512];
__device__ __nv_bfloat16 g_w2lo[512 * 512];
// Packed first-layer weights, transposed: [mat*512 + n][k], k = 0..1535
// mat 0: W1 top, 1: W1 bottom, 2: Ws1 top, 3: Ws1 bottom
__device__ __nv_bfloat16 g_prehi[4 * 512 * 1536];
__device__ __nv_bfloat16 g_prelo[4 * 512 * 1536];
// Packed entity matrix [m][k] bf16 hi/lo (m=512, k=1536)
__device__ __nv_bfloat16 g_enthi[512 * 1536];
__device__ __nv_bfloat16 g_entlo[512 * 1536];

// ---------------------------------------------------------------------------
// helpers
// ---------------------------------------------------------------------------
__device__ __forceinline__ void split4(float4 v, uint2& h, uint2& l) {
    __nv_bfloat16 hx = __float2bfloat16(v.x), hy = __float2bfloat16(v.y);
    __nv_bfloat16 hz = __float2bfloat16(v.z), hw = __float2bfloat16(v.w);
    __nv_bfloat16 lx = __float2bfloat16(v.x - __bfloat162float(hx));
    __nv_bfloat16 ly = __float2bfloat16(v.y - __bfloat162float(hy));
    __nv_bfloat16 lz = __float2bfloat16(v.z - __bfloat162float(hz));
    __nv_bfloat16 lw = __float2bfloat16(v.w - __bfloat162float(hw));
    __nv_bfloat162 h01; h01.x = hx; h01.y = hy;
    __nv_bfloat162 h23; h23.x = hz; h23.y = hw;
    __nv_bfloat162 l01; l01.x = lx; l01.y = ly;
    __nv_bfloat162 l23; l23.x = lz; l23.y = lw;
    h = make_uint2(*(uint32_t*)&h01, *(uint32_t*)&h23);
    l = make_uint2(*(uint32_t*)&l01, *(uint32_t*)&l23);
}

__device__ __forceinline__ void mma16816(float& c0, float& c1, float& c2, float& c3,
                                         uint32_t a0, uint32_t a1, uint32_t a2, uint32_t a3,
                                         uint32_t b0, uint32_t b1) {
    asm volatile(
        "mma.sync.aligned.m16n8k16.row.col.f32.bf16.bf16.f32 "
        "{%0,%1,%2,%3}, {%4,%5,%6,%7}, {%8,%9}, {%0,%1,%2,%3};"
        : "+f"(c0), "+f"(c1), "+f"(c2), "+f"(c3)
        : "r"(a0), "r"(a1), "r"(a2), "r"(a3), "r"(b0), "r"(b1));
}

// ---------------------------------------------------------------------------
// Kernel A: gather entity representations  ent[i] = [x[b,t0], x[b,t1]]
// and emit bf16 hi/lo packed copy for the precompute GEMM.
// ---------------------------------------------------------------------------
__global__ void k_gather(const float* __restrict__ x, const int* __restrict__ ann,
                         float* __restrict__ ent) {
    int i = blockIdx.x;
    int b = i >> 5, a = i & 31;
    int t0 = ann[b * 64 + 2 * a];
    int t1 = ann[b * 64 + 2 * a + 1];
    const float4* r0 = reinterpret_cast<const float4*>(x + ((long)b * TT + t0) * EE);
    const float4* r1 = reinterpret_cast<const float4*>(x + ((long)b * TT + t1) * EE);
    float4* o = reinterpret_cast<float4*>(ent + (long)i * TWO_E);
    __nv_bfloat16* eh = g_enthi + (long)i * TWO_E;
    __nv_bfloat16* el = g_entlo + (long)i * TWO_E;
    for (int j = threadIdx.x; j < 192; j += blockDim.x) {
        float4 v0 = r0[j];
        float4 v1 = r1[j];
        o[j] = v0;
        o[192 + j] = v1;
        uint2 h, l;
        split4(v0, h, l);
        *(uint2*)(eh + j * 4) = h;
        *(uint2*)(el + j * 4) = l;
        split4(v1, h, l);
        *(uint2*)(eh + 768 + j * 4) = h;
        *(uint2*)(el + 768 + j * 4) = l;
    }
}

// ---------------------------------------------------------------------------
// Pack W1/Ws1 into [mat*512+n][k] bf16 hi/lo (transposed).
// j -> n fastest (coalesced reads). 393216 jobs.
// ---------------------------------------------------------------------------
__global__ void k_packw1(const float* __restrict__ W1, const float* __restrict__ Ws1) {
    int j = blockIdx.x * 256 + threadIdx.x;
    int n = j & 511;
    int rest = j >> 9;
    int kg = rest % 192;
    int mat = rest / 192;
    const float* W = ((mat < 2) ? W1 : Ws1) + (long)(mat & 1) * (1536 * 512);
    int k0 = kg * 8;
    __nv_bfloat16 hi[8], lo[8];
#pragma unroll
    for (int q = 0; q < 8; q++) {
        float v = W[(long)(k0 + q) * 512 + n];
        hi[q] = __float2bfloat16(v);
        lo[q] = __float2bfloat16(v - __bfloat162float(hi[q]));
    }
    long off = (long)(mat * 512 + n) * 1536 + k0;
    *(uint4*)&g_prehi[off] = *(uint4*)hi;
    *(uint4*)&g_prelo[off] = *(uint4*)lo;
}

// ---------------------------------------------------------------------------
// Pack W2 (k-major [k][n]) into bf16 hi/lo [n][k].
// ---------------------------------------------------------------------------
__global__ void k_packw2(const float* __restrict__ W2) {
    int t = blockIdx.x * 256 + threadIdx.x;   // 0..131071
    int n = t >> 8;
    int k = (t & 255) * 2;
    float v0 = W2[(long)k * 512 + n];
    float v1 = W2[(long)(k + 1) * 512 + n];
    __nv_bfloat16 h0 = __float2bfloat16(v0), h1 = __float2bfloat16(v1);
    float r0 = v0 - __bfloat162float(h0);
    float r1 = v1 - __bfloat162float(h1);
    __nv_bfloat16 l0 = __float2bfloat16(r0), l1 = __float2bfloat16(r1);
    __nv_bfloat162 ph; ph.x = h0; ph.y = h1;
    __nv_bfloat162 pl; pl.x = l0; pl.y = l1;
    *(uint32_t*)&g_w2hi[(long)n * 512 + k] = *(uint32_t*)&ph;
    *(uint32_t*)&g_w2lo[(long)n * 512 + k] = *(uint32_t*)&pl;
}

#define PADK 40   // row stride in bf16 elements (80 bytes) -> conflict-free frags

// ---------------------------------------------------------------------------
// Kernel B (HMMA): precompute  g_scratch[mat] = ent @ W_block  (3xBF16)
// grid (32, 4): x = 64-col block over 2048 total cols, y = 128-row block
// block 256 (8 warps: 4 m x 2 n), warp tile 32m x 32n, K=1536 chunks of 32
// ---------------------------------------------------------------------------
__global__ void __launch_bounds__(256, 1) k_pre_hmma() {
    __shared__ __nv_bfloat16 sAh[128][PADK];
    __shared__ __nv_bfloat16 sAl[128][PADK];
    __shared__ __nv_bfloat16 sBh[64][PADK];
    __shared__ __nv_bfloat16 sBl[64][PADK];

    int tid = threadIdx.x;
    int wid = tid >> 5, lane = tid & 31;
    int g = lane >> 2, tq = lane & 3;
    int bm = blockIdx.y * 128;
    int nb = blockIdx.x;
    int wm = (wid & 3) * 32;
    int wn = (wid >> 2) * 32;

    // A load assignment: row m, 16-k half
    int m = tid >> 1;
    int kh = (tid & 1) * 16;
    const __nv_bfloat16* gAh = g_enthi + (long)(bm + m) * 1536 + kh;
    const __nv_bfloat16* gAl = g_entlo + (long)(bm + m) * 1536 + kh;
    // B load assignment: row br (of 64), 8-k quarter
    int br = tid >> 2;
    int koff = (tid & 3) * 8;
    int ng = nb * 64 + br;   // global col 0..2047 == packed row index
    const __nv_bfloat16* gBh = g_prehi + (long)ng * 1536 + koff;
    const __nv_bfloat16* gBl = g_prelo + (long)ng * 1536 + koff;

    float acc[2][4][4];
#pragma unroll
    for (int mt = 0; mt < 2; mt++)
#pragma unroll
        for (int nt = 0; nt < 4; nt++)
#pragma unroll
            for (int q = 0; q < 4; q++) acc[mt][nt][q] = 0.f;

    for (int kc = 0; kc < 1536; kc += 32) {
        uint4 ah0 = *(const uint4*)(gAh + kc);
        uint4 ah1 = *(const uint4*)(gAh + kc + 8);
        uint4 al0 = *(const uint4*)(gAl + kc);
        uint4 al1 = *(const uint4*)(gAl + kc + 8);
        uint4 bh = *(const uint4*)(gBh + kc);
        uint4 bl = *(const uint4*)(gBl + kc);

        __syncthreads();
        *(uint4*)&sAh[m][kh]     = ah0;
        *(uint4*)&sAh[m][kh + 8] = ah1;
        *(uint4*)&sAl[m][kh]     = al0;
        *(uint4*)&sAl[m][kh + 8] = al1;
        *(uint4*)&sBh[br][koff] = bh;
        *(uint4*)&sBl[br][koff] = bl;
        __syncthreads();

#pragma unroll
        for (int ks = 0; ks < 32; ks += 16) {
            uint32_t ah[2][4], al[2][4];
#pragma unroll
            for (int mt = 0; mt < 2; mt++) {
                int r0 = wm + mt * 16 + g;
                ah[mt][0] = *(uint32_t*)&sAh[r0][ks + 2 * tq];
                ah[mt][1] = *(uint32_t*)&sAh[r0 + 8][ks + 2 * tq];
                ah[mt][2] = *(uint32_t*)&sAh[r0][ks + 2 * tq + 8];
                ah[mt][3] = *(uint32_t*)&sAh[r0 + 8][ks + 2 * tq + 8];
                al[mt][0] = *(uint32_t*)&sAl[r0][ks + 2 * tq];
                al[mt][1] = *(uint32_t*)&sAl[r0 + 8][ks + 2 * tq];
                al[mt][2] = *(uint32_t*)&sAl[r0][ks + 2 * tq + 8];
                al[mt][3] = *(uint32_t*)&sAl[r0 + 8][ks + 2 * tq + 8];
            }
#pragma unroll
            for (int nt = 0; nt < 4; nt++) {
                int nr = wn + nt * 8 + g;
                uint32_t bh0 = *(uint32_t*)&sBh[nr][ks + 2 * tq];
                uint32_t bh1 = *(uint32_t*)&sBh[nr][ks + 2 * tq + 8];
                uint32_t bl0 = *(uint32_t*)&sBl[nr][ks + 2 * tq];
                uint32_t bl1 = *(uint32_t*)&sBl[nr][ks + 2 * tq + 8];
#pragma unroll
                for (int mt = 0; mt < 2; mt++) {
                    float* c = acc[mt][nt];
                    mma16816(c[0], c[1], c[2], c[3],
                             ah[mt][0], ah[mt][1], ah[mt][2], ah[mt][3], bh0, bh1);
                    mma16816(c[0], c[1], c[2], c[3],
                             ah[mt][0], ah[mt][1], ah[mt][2], ah[mt][3], bl0, bl1);
                    mma16816(c[0], c[1], c[2], c[3],
                             al[mt][0], al[mt][1], al[mt][2], al[mt][3], bh0, bh1);
                }
            }
        }
    }

    // store to g_scratch: col -> (mat = col>>9, cim = col&511)
#pragma unroll
    for (int nt = 0; nt < 4; nt++) {
        int col = nb * 64 + wn + nt * 8 + 2 * tq;
        long base = (long)(col >> 9) * 262144 + (col & 511);
#pragma unroll
        for (int mt = 0; mt < 2; mt++) {
            int row = bm + wm + mt * 16 + g;
            float* c = acc[mt][nt];
            *(float2*)&g_scratch[base + (long)row * 512] = make_float2(c[0], c[1]);
            *(float2*)&g_scratch[base + (long)(row + 8) * 512] = make_float2(c[2], c[3]);
        }
    }
}

// ---------------------------------------------------------------------------
// Kernel C (HMMA): relation_representation
//   CTA tile: M=128 pairs x N=128 cols, K=512 in chunks of 32.
//   H chunk = relu(A[l]+B[r]+b1) built SIMT, split bf16 hi/lo in SMEM.
//   3xBF16: acc += Ah*Bh + Ah*Bl + Al*Bh  (fp32 accum in registers).
// grid (4, 124), block 256 (8 warps: 4 m-warps x 2 n-warps)
// ---------------------------------------------------------------------------
__global__ void __launch_bounds__(256, 1) k_pairs_hmma(
    const int* __restrict__ left, const int* __restrict__ right,
    const float* __restrict__ b1, const float* __restrict__ b2,
    float* __restrict__ out_rel)
{
    __shared__ __nv_bfloat16 sAh[128][PADK];
    __shared__ __nv_bfloat16 sAl[128][PADK];
    __shared__ __nv_bfloat16 sBh[128][PADK];
    __shared__ __nv_bfloat16 sBl[128][PADK];
    __shared__ float b1s[512];

    int tid = threadIdx.x;
    int wid = tid >> 5, lane = tid & 31;
    int g = lane >> 2, tq = lane & 3;
    int bp = blockIdx.y * 128;
    int nb = blockIdx.x;           // n block (128 cols)
    int wm = (wid & 3) * 32;       // warp m offset
    int wn = (wid >> 2) * 64;      // warp n offset

    // H-build assignment
    int m = tid >> 1;
    int kh = (tid & 1) * 16;
    int lm = left[bp + m];
    int rm = right[bp + m];
    const float* Ar = g_scratch + (long)lm * 512;
    const float* Br = g_scratch + 262144 + (long)rm * 512;

    // B-tile load assignment: row r, half (tid&1)
    int br = tid >> 1;
    int bh_off = (tid & 1) * 16;
    const __nv_bfloat16* gBh = g_w2hi + (long)(nb * 128 + br) * 512 + bh_off;
    const __nv_bfloat16* gBl = g_w2lo + (long)(nb * 128 + br) * 512 + bh_off;

    if (tid < 128) ((float4*)b1s)[tid] = ((const float4*)b1)[tid];
    __syncthreads();   // b1s visible to ALL warps before first H-build (race fix)

    float acc[2][8][4];
#pragma unroll
    for (int mt = 0; mt < 2; mt++)
#pragma unroll
        for (int nt = 0; nt < 8; nt++)
#pragma unroll
            for (int q = 0; q < 4; q++) acc[mt][nt][q] = 0.f;

    for (int kc = 0; kc < 512; kc += 32) {
        // ---- stage B chunk through registers (overlap with H build) ----
        uint4 wbh0 = *(const uint4*)(gBh + kc);
        uint4 wbh1 = *(const uint4*)(gBh + kc + 8);
        uint4 wbl0 = *(const uint4*)(gBl + kc);
        uint4 wbl1 = *(const uint4*)(gBl + kc + 8);

        // ---- build H (relu(A[l]+B[r]+b1)), split hi/lo ----
        int kg = kc + kh;
        float4 x0 = *(const float4*)(Ar + kg);
        float4 x1 = *(const float4*)(Ar + kg + 4);
        float4 x2 = *(const float4*)(Ar + kg + 8);
        float4 x3 = *(const float4*)(Ar + kg + 12);
        float4 y0 = *(const float4*)(Br + kg);
        float4 y1 = *(const float4*)(Br + kg + 4);
        float4 y2 = *(const float4*)(Br + kg + 8);
        float4 y3 = *(const float4*)(Br + kg + 12);
        float h[16];
        h[0]  = x0.x + y0.x; h[1]  = x0.y + y0.y; h[2]  = x0.z + y0.z; h[3]  = x0.w + y0.w;
        h[4]  = x1.x + y1.x; h[5]  = x1.y + y1.y; h[6]  = x1.z + y1.z; h[7]  = x1.w + y1.w;
        h[8]  = x2.x + y2.x; h[9]  = x2.y + y2.y; h[10] = x2.z + y2.z; h[11] = x2.w + y2.w;
        h[12] = x3.x + y3.x; h[13] = x3.y + y3.y; h[14] = x3.z + y3.z; h[15] = x3.w + y3.w;
        uint32_t hiw[8], low[8];
#pragma unroll
        for (int q = 0; q < 8; q++) {
            float v0 = fmaxf(h[2 * q]     + b1s[kg + 2 * q],     0.f);
            float v1 = fmaxf(h[2 * q + 1] + b1s[kg + 2 * q + 1], 0.f);
            __nv_bfloat16 e0 = __float2bfloat16(v0);
            __nv_bfloat16 e1 = __float2bfloat16(v1);
            __nv_bfloat16 f0 = __float2bfloat16(v0 - __bfloat162float(e0));
            __nv_bfloat16 f1 = __float2bfloat16(v1 - __bfloat162float(e1));
            __nv_bfloat162 ph; ph.x = e0; ph.y = e1;
            __nv_bfloat162 pl; pl.x = f0; pl.y = f1;
            hiw[q] = *(uint32_t*)&ph;
            low[q] = *(uint32_t*)&pl;
        }

        __syncthreads();   // previous chunk's MMAs done reading SMEM

        *(uint4*)&sAh[m][kh]     = make_uint4(hiw[0], hiw[1], hiw[2], hiw[3]);
        *(uint4*)&sAh[m][kh + 8] = make_uint4(hiw[4], hiw[5], hiw[6], hiw[7]);
        *(uint4*)&sAl[m][kh]     = make_uint4(low[0], low[1], low[2], low[3]);
        *(uint4*)&sAl[m][kh + 8] = make_uint4(low[4], low[5], low[6], low[7]);
        *(uint4*)&sBh[br][bh_off]     = wbh0;
        *(uint4*)&sBh[br][bh_off + 8] = wbh1;
        *(uint4*)&sBl[br][bh_off]     = wbl0;
        *(uint4*)&sBl[br][bh_off + 8] = wbl1;

        __syncthreads();

        // ---- MMA over the 32-wide chunk (two k16 steps) ----
#pragma unroll
        for (int ks = 0; ks < 32; ks += 16) {
            uint32_t ah[2][4], al[2][4];
#pragma unroll
            for (int mt = 0; mt < 2; mt++) {
                int r0 = wm + mt * 16 + g;
                ah[mt][0] = *(uint32_t*)&sAh[r0][ks + 2 * tq];
                ah[mt][1] = *(uint32_t*)&sAh[r0 + 8][ks + 2 * tq];
                ah[mt][2] = *(uint32_t*)&sAh[r0][ks + 2 * tq + 8];
                ah[mt][3] = *(uint32_t*)&sAh[r0 + 8][ks + 2 * tq + 8];
                al[mt][0] = *(uint32_t*)&sAl[r0][ks + 2 * tq];
                al[mt][1] = *(uint32_t*)&sAl[r0 + 8][ks + 2 * tq];
                al[mt][2] = *(uint32_t*)&sAl[r0][ks + 2 * tq + 8];
                al[mt][3] = *(uint32_t*)&sAl[r0 + 8][ks + 2 * tq + 8];
            }
#pragma unroll
            for (int nt = 0; nt < 8; nt++) {
                int nr = wn + nt * 8 + g;
                uint32_t bh0 = *(uint32_t*)&sBh[nr][ks + 2 * tq];
                uint32_t bh1 = *(uint32_t*)&sBh[nr][ks + 2 * tq + 8];
                uint32_t bl0 = *(uint32_t*)&sBl[nr][ks + 2 * tq];
                uint32_t bl1 = *(uint32_t*)&sBl[nr][ks + 2 * tq + 8];
#pragma unroll
                for (int mt = 0; mt < 2; mt++) {
                    float* c = acc[mt][nt];
                    mma16816(c[0], c[1], c[2], c[3],
                             ah[mt][0], ah[mt][1], ah[mt][2], ah[mt][3], bh0, bh1);
                    mma16816(c[0], c[1], c[2], c[3],
                             ah[mt][0], ah[mt][1], ah[mt][2], ah[mt][3], bl0, bl1);
                    mma16816(c[0], c[1], c[2], c[3],
                             al[mt][0], al[mt][1], al[mt][2], al[mt][3], bh0, bh1);
                }
            }
        }
    }

    // ---- epilogue: add b2, store ----
#pragma unroll
    for (int nt = 0; nt < 8; nt++) {
        int col = nb * 128 + wn + nt * 8 + 2 * tq;
        float bb0 = __ldg(&b2[col]);
        float bb1 = __ldg(&b2[col + 1]);
#pragma unroll
        for (int mt = 0; mt < 2; mt++) {
            int row = bp + wm + mt * 16 + g;
            float* c = acc[mt][nt];
            float2 v0 = make_float2(c[0] + bb0, c[1] + bb1);
            float2 v1 = make_float2(c[2] + bb0, c[3] + bb1);
            *(float2*)(out_rel + (long)row * 512 + col) = v0;
            *(float2*)(out_rel + (long)(row + 8) * 512 + col) = v1;
        }
    }
}

// ---------------------------------------------------------------------------
// Kernel D: relation_score.  One warp per pair.
// ---------------------------------------------------------------------------
__global__ void k_score(const int* __restrict__ left, const int* __restrict__ right,
                        const float* __restrict__ bs1, const float* __restrict__ Ws2,
                        const float* __restrict__ bs2, float* __restrict__ score) {
    const float* Asc = g_scratch + 2 * 512 * 512;
    const float* Bsc = g_scratch + 3 * 512 * 512;
    int warp = threadIdx.x >> 5, lane = threadIdx.x & 31;
    int p = blockIdx.x * 8 + warp;
    if (p >= PTOT) return;
    long l = left[p], r = right[p];
    float s = 0.f;
#pragma unroll
    for (int k = lane * 4; k < 512; k += 128) {
        float4 a = *reinterpret_cast<const float4*>(Asc + l * 512 + k);
        float4 b = *reinterpret_cast<const float4*>(Bsc + r * 512 + k);
        float4 bb = *reinterpret_cast<const float4*>(bs1 + k);
        float4 w = *reinterpret_cast<const float4*>(Ws2 + k);
        s = fmaf(fmaxf(a.x + b.x + bb.x, 0.f), w.x, s);
        s = fmaf(fmaxf(a.y + b.y + bb.y, 0.f), w.y, s);
        s = fmaf(fmaxf(a.z + b.z + bb.z, 0.f), w.z, s);
        s = fmaf(fmaxf(a.w + b.w + bb.w, 0.f), w.w, s);
    }
#pragma unroll
    for (int o = 16; o > 0; o >>= 1) s += __shfl_down_sync(0xffffffffu, s, o);
    if (lane == 0) score[p] = fabsf(s + bs2[0]);
}

// ---------------------------------------------------------------------------
extern "C" void kernel_launch(void* const* d_in, const int* in_sizes, int n_in,
                              void* d_out, int out_size) {
    const float* x   = (const float*)d_in[0];
    const int*   ann = (const int*)d_in[3];
    int p = (in_sizes[4] == 1) ? 5 : 4;
    const int*   left  = (const int*)d_in[p + 0];
    const int*   right = (const int*)d_in[p + 1];
    const float* W1  = (const float*)d_in[p + 2];
    const float* b1  = (const float*)d_in[p + 3];
    const float* W2  = (const float*)d_in[p + 4];
    const float* b2  = (const float*)d_in[p + 5];
    const float* Ws1 = (const float*)d_in[p + 6];
    const float* bs1 = (const float*)d_in[p + 7];
    const float* Ws2 = (const float*)d_in[p + 8];
    const float* bs2 = (const float*)d_in[p + 9];

    float* out   = (float*)d_out;
    float* ent   = out;                                  // [512, 1536]
    float* rel   = out + (long)NENT * TWO_E;             // [15872, 512]
    float* score = rel + (long)PTOT * OUTD;              // [15872]

    k_packw1<<<1536, 256>>>(W1, Ws1);
    k_packw2<<<512, 256>>>(W2);
    k_gather<<<NENT, 192>>>(x, ann, ent);
    k_pre_hmma<<<dim3(32, 4), 256>>>();
    k_pairs_hmma<<<dim3(4, 124), 256>>>(left, right, b1, b2, rel);
    k_score<<<PTOT / 8, 256>>>(left, right, bs1, Ws2, bs2, score);
}